// round 2
// baseline (speedup 1.0000x reference)
#include <cuda_runtime.h>
#include <math.h>

#define Nn 8
#define Cc 128
#define Hh 112
#define Ww 112
#define HW (Hh*Ww)          /* 12544 */
#define CHW (Cc*HW)         /* 1605632 */
#define NTOT (Nn*CHW)       /* 12845056 */

// scratch (static __device__ = allowed; no runtime allocs)
__device__ float g_t2[NTOT];              // silu(x)
__device__ float g_t3[NTOT];              // 1x3 dilated conv out
__device__ float g_t4[NTOT];              // depthwise 7x1 conv out
__device__ float g_t5[Nn*Cc*Cc];          // raw channel-attention sums
__device__ float g_w3t[Cc*Cc*3];          // w3 transposed: [(i*3+k)][o]
__device__ float g_weff[7*32*Cc];         // fused t15 weights: [k][cc][o]

// ---------------------------------------------------------------------------
// K1: t2 = x * sigmoid(x)
// ---------------------------------------------------------------------------
__global__ void k_silu(const float* __restrict__ x) {
    int i = blockIdx.x * blockDim.x + threadIdx.x;
    if (i >= NTOT/4) return;
    float4 v = reinterpret_cast<const float4*>(x)[i];
    float4 r;
    r.x = v.x / (1.f + __expf(-v.x));
    r.y = v.y / (1.f + __expf(-v.y));
    r.z = v.z / (1.f + __expf(-v.z));
    r.w = v.w / (1.f + __expf(-v.w));
    reinterpret_cast<float4*>(g_t2)[i] = r;
}

// ---------------------------------------------------------------------------
// K2: prep — transpose w3, build fused t15 weights, zero t5 accumulator
//   g_w3t[(i*3+k)*128 + o] = w3[o,i,k]
//   g_weff[(k*32+cc)*128 + o] = w15[o, cc*7+k] * w10[(o/32)*32+cc, k]
// ---------------------------------------------------------------------------
__global__ void k_prep(const float* __restrict__ w3, const float* __restrict__ w10,
                       const float* __restrict__ w15) {
    int i = blockIdx.x * blockDim.x + threadIdx.x;
    if (i < Cc*Cc*3) {
        int o = i & 127, r = i >> 7;           // r = i*3+k  (0..383)
        g_w3t[i] = w3[o*384 + r];
    }
    if (i < 7*32*Cc) {
        int o = i & 127, q = i >> 7;
        int k = q >> 5, cc = q & 31;
        int cabs = ((o >> 5) << 5) + cc;
        g_weff[i] = w15[o*224 + cc*7 + k] * w10[cabs*7 + k];
    }
    if (i < Nn*Cc*Cc) g_t5[i] = 0.f;
}

// ---------------------------------------------------------------------------
// K3: t5[n,c,d] = sum_s sigmoid(x[n,c,s]) * x[n,d,s]   (raw; scaled in K6)
// grid (28 s-chunks, 8 n), 256 thr, 8x8 register tile, k-split w/ atomic acc
// A and B smem tiles come from ONE global read of the same x slice.
// ---------------------------------------------------------------------------
__global__ void __launch_bounds__(256) k_t5(const float* __restrict__ x) {
    __shared__ float As[16][132];   // sigmoid(x) tile, [s_sub][c], padded
    __shared__ float Bs[16][132];   // raw x tile
    int n = blockIdx.y;
    int s0 = blockIdx.x * 448;
    int tid = threadIdx.x;
    int tx = tid & 15, ty = tid >> 4;
    const float* xb = x + (size_t)n * CHW;
    float acc[8][8];
    #pragma unroll
    for (int i = 0; i < 8; i++)
        #pragma unroll
        for (int j = 0; j < 8; j++) acc[i][j] = 0.f;

    int lc  = tid >> 1;
    int lso = (tid & 1) * 8;
    for (int kt = 0; kt < 448; kt += 16) {
        const float* src = xb + (size_t)lc * HW + (s0 + kt + lso);
        float4 v0 = *reinterpret_cast<const float4*>(src);
        float4 v1 = *reinterpret_cast<const float4*>(src + 4);
        float vv[8] = {v0.x, v0.y, v0.z, v0.w, v1.x, v1.y, v1.z, v1.w};
        __syncthreads();
        #pragma unroll
        for (int i = 0; i < 8; i++) {
            Bs[lso+i][lc] = vv[i];
            As[lso+i][lc] = 1.f / (1.f + __expf(-vv[i]));
        }
        __syncthreads();
        #pragma unroll
        for (int k = 0; k < 16; k++) {
            float a[8], b[8];
            #pragma unroll
            for (int i = 0; i < 4; i++) {
                a[i]   = As[k][ty*4 + i];
                a[4+i] = As[k][ty*4 + 64 + i];
                b[i]   = Bs[k][tx*4 + i];
                b[4+i] = Bs[k][tx*4 + 64 + i];
            }
            #pragma unroll
            for (int i = 0; i < 8; i++)
                #pragma unroll
                for (int j = 0; j < 8; j++)
                    acc[i][j] += a[i] * b[j];
        }
    }
    float* t5b = g_t5 + n * (Cc*Cc);
    #pragma unroll
    for (int i = 0; i < 8; i++) {
        int c = ty*4 + (i < 4 ? i : 60 + i);
        #pragma unroll
        for (int j = 0; j < 8; j++) {
            int d = tx*4 + (j < 4 ? j : 60 + j);
            atomicAdd(&t5b[c*128 + d], acc[i][j]);
        }
    }
}

// ---------------------------------------------------------------------------
// K4: t3[n,o,h,w] = sum_{i,k} w3[o,i,k] * t2[n,i,h, w+2k-2]  (zero pad in w)
// grid (112 h, 8 n), 256 thr (16x16), thread tile 8(o) x 7(w)
// ---------------------------------------------------------------------------
__global__ void __launch_bounds__(256) k_conv3() {
    extern __shared__ float sm[];
    float* rowb = sm;              // [128][116], 2-zero-pad both sides of w
    float* wsh  = sm + 128*116;    // [96][128] = w3t chunk (32 i x 3 k)
    int h = blockIdx.x, n = blockIdx.y;
    int tid = threadIdx.x, tx = tid & 15, ty = tid >> 4;

    for (int i = tid; i < 128*116; i += 256) rowb[i] = 0.f;
    __syncthreads();
    const float* t2row = g_t2 + (size_t)n * CHW + (size_t)h * Ww;
    for (int i = tid; i < 128*112; i += 256) {
        int c = i / 112, w = i - c*112;
        rowb[c*116 + 2 + w] = t2row[(size_t)c * HW + w];
    }

    float acc[8][7];
    #pragma unroll
    for (int i = 0; i < 8; i++)
        #pragma unroll
        for (int j = 0; j < 7; j++) acc[i][j] = 0.f;

    for (int i0 = 0; i0 < 128; i0 += 32) {
        __syncthreads();
        #pragma unroll 4
        for (int i = tid; i < 96*128; i += 256)
            wsh[i] = g_w3t[i0*384 + i];
        __syncthreads();
        #pragma unroll 2
        for (int ic = 0; ic < 32; ic++) {
            #pragma unroll
            for (int k = 0; k < 3; k++) {
                const float* wrow = wsh + (ic*3 + k)*128;
                float a[8];
                #pragma unroll
                for (int i = 0; i < 4; i++) { a[i] = wrow[ty*4+i]; a[4+i] = wrow[ty*4+64+i]; }
                const float* br = rowb + (i0 + ic)*116 + 2*k + tx;   // FIX: absolute channel
                #pragma unroll
                for (int j = 0; j < 7; j++) {
                    float b = br[16*j];
                    #pragma unroll
                    for (int i = 0; i < 8; i++) acc[i][j] += a[i]*b;
                }
            }
        }
    }
    float* dst = g_t3 + (size_t)n*CHW + (size_t)h*Ww;
    #pragma unroll
    for (int i = 0; i < 8; i++) {
        int o = ty*4 + (i < 4 ? i : 60 + i);
        #pragma unroll
        for (int j = 0; j < 7; j++)
            dst[(size_t)o*HW + tx + 16*j] = acc[i][j];
    }
}

// ---------------------------------------------------------------------------
// K5: t4 = depthwise conv (7,1), dil (3,1), pad (9,0) on t3
// ---------------------------------------------------------------------------
__global__ void k_conv4(const float* __restrict__ w4) {
    int idx = blockIdx.x * blockDim.x + threadIdx.x;
    if (idx >= NTOT) return;
    int w  = idx % Ww;
    int t  = idx / Ww;
    int h  = t % Hh;
    int nc = t / Hh;            // n*128 + c
    int c  = nc & 127;
    const float* base = g_t3 + (size_t)nc * HW;
    float wk[7];
    #pragma unroll
    for (int k = 0; k < 7; k++) wk[k] = __ldg(&w4[c*7 + k]);
    float acc = 0.f;
    #pragma unroll
    for (int k = 0; k < 7; k++) {
        int hh = h - 9 + 3*k;
        if (hh >= 0 && hh < Hh) acc += base[hh*Ww + w] * wk[k];
    }
    g_t4[idx] = acc;
}

// ---------------------------------------------------------------------------
// K6: out[n,d,h,w] = (1/sqrt(c)) sum_c (w9[c,d]*t5[n,c,d]/sqrt(hw)) * t2[n,c,h,w]
// grid (112 h, 8 n), thread tile 8(d) x 7(w). Writes d_out (first writer).
// ---------------------------------------------------------------------------
__global__ void __launch_bounds__(256) k_t14(const float* __restrict__ w9,
                                             float* __restrict__ out) {
    extern __shared__ float sm[];
    float* Am   = sm;              // [128 c][128 d]
    float* rowb = sm + 128*128;    // [128 c][112 w]
    int h = blockIdx.x, n = blockIdx.y;
    int tid = threadIdx.x, tx = tid & 15, ty = tid >> 4;
    const float SCALE = 1.0f / (112.0f * 11.313708498984761f); // 1/(sqrt(hw)*sqrt(c))
    const float* t5b = g_t5 + n*(Cc*Cc);
    for (int i = tid; i < 128*128; i += 256) Am[i] = t5b[i] * w9[i] * SCALE;
    const float* t2row = g_t2 + (size_t)n*CHW + (size_t)h*Ww;
    for (int i = tid; i < 128*112; i += 256) {
        int c = i / 112, w = i - c*112;
        rowb[c*112 + w] = t2row[(size_t)c*HW + w];
    }
    __syncthreads();
    float acc[8][7];
    #pragma unroll
    for (int i = 0; i < 8; i++)
        #pragma unroll
        for (int j = 0; j < 7; j++) acc[i][j] = 0.f;
    #pragma unroll 4
    for (int c = 0; c < 128; c++) {
        const float* ar = Am + c*128;
        float a[8];
        #pragma unroll
        for (int i = 0; i < 4; i++) { a[i] = ar[ty*4+i]; a[4+i] = ar[ty*4+64+i]; }
        const float* br = rowb + c*112 + tx;
        #pragma unroll
        for (int j = 0; j < 7; j++) {
            float b = br[16*j];
            #pragma unroll
            for (int i = 0; i < 8; i++) acc[i][j] += a[i]*b;
        }
    }
    float* dst = out + (size_t)n*CHW + (size_t)h*Ww;
    #pragma unroll
    for (int i = 0; i < 8; i++) {
        int d = ty*4 + (i < 4 ? i : 60 + i);
        #pragma unroll
        for (int j = 0; j < 7; j++)
            dst[(size_t)d*HW + tx + 16*j] = acc[i][j];
    }
}

// ---------------------------------------------------------------------------
// K7: out += t15.   t15[n,o,h,w] = sum_{k,cc} Weff[o,k,cc] *
//        t4[n, (g*32+cc-2)&127, ((h+2)%112)+2k-6, (w-2)%112]   (row OOB -> 0)
// grid (112 h, 8 n), thread tile 8(o, contiguous, same group) x 7(w)
// ---------------------------------------------------------------------------
__global__ void __launch_bounds__(256) k_t15(float* __restrict__ out) {
    extern __shared__ float sm[];
    float* rowb = sm;            // [128 c][112 w] : t4 row r
    float* wsm  = sm + 128*112;  // [32 cc][128 o] : Weff slice for k
    int h = blockIdx.x, n = blockIdx.y;
    int tid = threadIdx.x, tx = tid & 15, ty = tid >> 4;
    int gbase = (ty >> 2) * 32;     // group base channel of this thread's 8 o's
    int h2 = (h + 2) % Hh;
    int wcol[7];
    #pragma unroll
    for (int j = 0; j < 7; j++) wcol[j] = (tx + 16*j + 110) % 112;  // (w-2) mod 112
    float acc[8][7];
    #pragma unroll
    for (int i = 0; i < 8; i++)
        #pragma unroll
        for (int j = 0; j < 7; j++) acc[i][j] = 0.f;

    for (int k = 0; k < 7; k++) {
        int r = h2 + 2*k - 6;
        if (r < 0 || r >= Hh) continue;   // uniform across block
        __syncthreads();
        const float* t4row = g_t4 + (size_t)n*CHW + (size_t)r*Ww;
        for (int i = tid; i < 128*112; i += 256) {
            int c = i / 112, w = i - c*112;
            rowb[c*112 + w] = t4row[(size_t)c*HW + w];
        }
        for (int i = tid; i < 32*128; i += 256) wsm[i] = g_weff[k*4096 + i];
        __syncthreads();
        #pragma unroll 4
        for (int cc = 0; cc < 32; cc++) {
            int c2 = (gbase + cc - 2) & 127;
            const float* ar = wsm + cc*128 + ty*8;
            float a[8];
            #pragma unroll
            for (int i = 0; i < 8; i++) a[i] = ar[i];
            const float* br = rowb + c2*112;
            #pragma unroll
            for (int j = 0; j < 7; j++) {
                float b = br[wcol[j]];
                #pragma unroll
                for (int i = 0; i < 8; i++) acc[i][j] += a[i]*b;
            }
        }
    }
    float* dst = out + (size_t)n*CHW + (size_t)h*Ww;
    #pragma unroll
    for (int i = 0; i < 8; i++) {
        int o = ty*8 + i;
        #pragma unroll
        for (int j = 0; j < 7; j++)
            dst[(size_t)o*HW + tx + 16*j] += acc[i][j];
    }
}

// ---------------------------------------------------------------------------
extern "C" void kernel_launch(void* const* d_in, const int* in_sizes, int n_in,
                              void* d_out, int out_size) {
    const float* x   = (const float*)d_in[0];
    const float* w3  = (const float*)d_in[1];
    const float* w4  = (const float*)d_in[2];
    const float* w9  = (const float*)d_in[3];
    const float* w10 = (const float*)d_in[4];
    const float* w15 = (const float*)d_in[5];
    float* out = (float*)d_out;

    const int SMEM3  = (128*116 + 96*128) * 4;   // 108544
    const int SMEM14 = (128*128 + 128*112) * 4;  // 122880
    const int SMEM15 = (128*112 + 32*128) * 4;   // 73728
    cudaFuncSetAttribute(k_conv3, cudaFuncAttributeMaxDynamicSharedMemorySize, SMEM3);
    cudaFuncSetAttribute(k_t14,   cudaFuncAttributeMaxDynamicSharedMemorySize, SMEM14);
    cudaFuncSetAttribute(k_t15,   cudaFuncAttributeMaxDynamicSharedMemorySize, SMEM15);

    k_silu <<< NTOT/4/256, 256 >>>(x);
    k_prep <<< 512, 256 >>>(w3, w10, w15);
    k_t5   <<< dim3(28, 8), 256 >>>(x);
    k_conv3<<< dim3(112, 8), 256, SMEM3 >>>();
    k_conv4<<< (NTOT + 255)/256, 256 >>>(w4);
    k_t14  <<< dim3(112, 8), 256, SMEM14 >>>(w9, out);
    k_t15  <<< dim3(112, 8), 256, SMEM15 >>>(out);
}

// round 4
// speedup vs baseline: 1.0578x; 1.0578x over previous
#include <cuda_runtime.h>
#include <cuda_bf16.h>
#include <cstdint>
#include <cstddef>
#include <math.h>

typedef unsigned int u32;

#define Nn 8
#define Cc 128
#define Hh 112
#define Ww 112
#define HW (Hh*Ww)          /* 12544 */
#define CHW (Cc*HW)         /* 1605632 */
#define NTOT (Nn*CHW)       /* 12845056 */
#define T2T_ROW 116
#define T2T_H (T2T_ROW*Cc)  /* 14848 per (n,h) */

// ---- global scratch (static __device__ = allowed) ----
__device__ float g_t3[NTOT];
__device__ float g_t4[NTOT];
__device__ float g_t5[Nn*Cc*Cc];
__device__ float g_weff[7*32*Cc];
__device__ __nv_bfloat16 g_t2Th[(size_t)Nn*Hh*T2T_H];  // silu(x) transposed [n][h][w'][c], hi
__device__ __nv_bfloat16 g_t2Tl[(size_t)Nn*Hh*T2T_H];  // lo residual
__device__ __nv_bfloat16 g_w3h[3*Cc*Cc];               // [kk][o][i]
__device__ __nv_bfloat16 g_w3l[3*Cc*Cc];
__device__ __nv_bfloat16 g_amh[Nn*Cc*Cc];              // t14 A = w9*t5*scale, [n][d][c]
__device__ __nv_bfloat16 g_aml[Nn*Cc*Cc];

// ---- mma helpers ----
__device__ __forceinline__ u32 smem_u32(const void* p) {
    return (u32)__cvta_generic_to_shared(p);
}
__device__ __forceinline__ void ldsm4(u32& r0, u32& r1, u32& r2, u32& r3, u32 a) {
    asm volatile("ldmatrix.sync.aligned.m8n8.x4.shared.b16 {%0,%1,%2,%3},[%4];\n"
                 : "=r"(r0), "=r"(r1), "=r"(r2), "=r"(r3) : "r"(a));
}
__device__ __forceinline__ void ldsm2(u32& r0, u32& r1, u32 a) {
    asm volatile("ldmatrix.sync.aligned.m8n8.x2.shared.b16 {%0,%1},[%2];\n"
                 : "=r"(r0), "=r"(r1) : "r"(a));
}
__device__ __forceinline__ void mma16816(float* c, u32 a0, u32 a1, u32 a2, u32 a3,
                                         u32 b0, u32 b1) {
    asm volatile("mma.sync.aligned.m16n8k16.row.col.f32.bf16.bf16.f32 "
                 "{%0,%1,%2,%3},{%4,%5,%6,%7},{%8,%9},{%0,%1,%2,%3};\n"
                 : "+f"(c[0]), "+f"(c[1]), "+f"(c[2]), "+f"(c[3])
                 : "r"(a0), "r"(a1), "r"(a2), "r"(a3), "r"(b0), "r"(b1));
}
__device__ __forceinline__ void bsplit(float v, __nv_bfloat16& hi, __nv_bfloat16& lo) {
    hi = __float2bfloat16(v);
    lo = __float2bfloat16(v - __bfloat162float(hi));
}

// ---------------------------------------------------------------------------
// K1: silu(x) -> transposed bf16 hi/lo [n][h][w'][c], w' = w+2, zero-padded
// ---------------------------------------------------------------------------
__global__ void __launch_bounds__(256) k_silu_t(const float* __restrict__ x) {
    extern __shared__ float xs[];   // [128][113]
    int h = blockIdx.x, n = blockIdx.y, tid = threadIdx.x;
    const float* xr = x + (size_t)n * CHW + (size_t)h * Ww;
    for (int i = tid; i < 128 * 112; i += 256) {
        int c = i / 112, w = i - c * 112;
        xs[c * 113 + w] = xr[(size_t)c * HW + w];
    }
    __syncthreads();
    size_t base = ((size_t)(n * Hh + h)) * T2T_H;
    for (int i = tid; i < T2T_H; i += 256) {
        int wp = i >> 7, c = i & 127;
        float v = 0.f;
        if (wp >= 2 && wp < 114) {
            float u = xs[c * 113 + (wp - 2)];
            v = u / (1.f + __expf(-u));
        }
        __nv_bfloat16 hh, ll;
        bsplit(v, hh, ll);
        g_t2Th[base + i] = hh;
        g_t2Tl[base + i] = ll;
    }
}

// ---------------------------------------------------------------------------
// K2: prep — split w3 -> [kk][o][i] bf16 hi/lo, fuse t15 weights, zero t5
// ---------------------------------------------------------------------------
__global__ void k_prep(const float* __restrict__ w3, const float* __restrict__ w10,
                       const float* __restrict__ w15) {
    int i = blockIdx.x * blockDim.x + threadIdx.x;
    if (i < 3 * 128 * 128) {
        int ii = i & 127, o = (i >> 7) & 127, kk = i >> 14;
        float v = w3[o * 384 + ii * 3 + kk];
        __nv_bfloat16 hh, ll;
        bsplit(v, hh, ll);
        g_w3h[i] = hh;
        g_w3l[i] = ll;
    }
    if (i < 7 * 32 * 128) {
        int o = i & 127, q = i >> 7;
        int k = q >> 5, cc = q & 31;
        int cabs = ((o >> 5) << 5) + cc;
        g_weff[i] = w15[o * 224 + cc * 7 + k] * w10[cabs * 7 + k];
    }
    if (i < Nn * 128 * 128) g_t5[i] = 0.f;
}

// ---------------------------------------------------------------------------
// K3: t5[n,c,d] = sum_s sig(x[n,c,s]) * x[n,d,s]  (raw; scaled in prep2)
// mma bf16x3; grid (28 s-chunks, 8 n), 8 warps as 2(M)x4(N), K-split atomics
// ---------------------------------------------------------------------------
__global__ void __launch_bounds__(256) k_t5(const float* __restrict__ x) {
    extern __shared__ __nv_bfloat16 sm5[];
    __nv_bfloat16* sAh = sm5;                 // sig hi [128][72]
    __nv_bfloat16* sAl = sm5 + 128 * 72;
    __nv_bfloat16* sBh = sm5 + 2 * 128 * 72;  // x hi
    __nv_bfloat16* sBl = sm5 + 3 * 128 * 72;
    int n = blockIdx.y, tid = threadIdx.x, lane = tid & 31, warp = tid >> 5;
    int wm = warp >> 2, wn = warp & 3;
    int s0 = blockIdx.x * 448;
    const float* xb = x + (size_t)n * CHW;

    float acc[4][4][4];
    #pragma unroll
    for (int a = 0; a < 4; a++)
        #pragma unroll
        for (int b = 0; b < 4; b++)
            #pragma unroll
            for (int c = 0; c < 4; c++) acc[a][b][c] = 0.f;

    int qa_row = (lane & 7) + ((lane >> 3) & 1) * 8;
    int qa_col = (lane >> 4) * 8;
    int lb = lane & 15;
    int qb_row = lb & 7, qb_col = (lb >> 3) * 8;
    u32 aH = smem_u32(sAh), aL = smem_u32(sAl), bH = smem_u32(sBh), bL = smem_u32(sBl);

    for (int st = 0; st < 7; st++) {
        int sb = s0 + st * 64;
        __syncthreads();
        for (int i = tid; i < 128 * 16; i += 256) {
            int c = i >> 4, q = i & 15;
            float4 v = *reinterpret_cast<const float4*>(xb + (size_t)c * HW + sb + 4 * q);
            float u[4] = {v.x, v.y, v.z, v.w};
            #pragma unroll
            for (int j = 0; j < 4; j++) {
                int idx = c * 72 + 4 * q + j;
                float s = 1.f / (1.f + __expf(-u[j]));
                __nv_bfloat16 hh, ll;
                bsplit(s, hh, ll);
                sAh[idx] = hh; sAl[idx] = ll;
                bsplit(u[j], hh, ll);
                sBh[idx] = hh; sBl[idx] = ll;
            }
        }
        __syncthreads();
        #pragma unroll
        for (int k0 = 0; k0 < 64; k0 += 16) {
            u32 ah[4][4], al[4][4], bh[4][2], bl[4][2];
            #pragma unroll
            for (int mt = 0; mt < 4; mt++) {
                u32 off = (u32)(((wm * 64 + mt * 16 + qa_row) * 72 + k0 + qa_col) * 2);
                ldsm4(ah[mt][0], ah[mt][1], ah[mt][2], ah[mt][3], aH + off);
                ldsm4(al[mt][0], al[mt][1], al[mt][2], al[mt][3], aL + off);
            }
            #pragma unroll
            for (int nt = 0; nt < 4; nt++) {
                u32 off = (u32)(((wn * 32 + nt * 8 + qb_row) * 72 + k0 + qb_col) * 2);
                ldsm2(bh[nt][0], bh[nt][1], bH + off);
                ldsm2(bl[nt][0], bl[nt][1], bL + off);
            }
            #pragma unroll
            for (int mt = 0; mt < 4; mt++) {
                #pragma unroll
                for (int nt = 0; nt < 4; nt++) {
                    mma16816(acc[mt][nt], ah[mt][0], ah[mt][1], ah[mt][2], ah[mt][3], bh[nt][0], bh[nt][1]);
                    mma16816(acc[mt][nt], ah[mt][0], ah[mt][1], ah[mt][2], ah[mt][3], bl[nt][0], bl[nt][1]);
                    mma16816(acc[mt][nt], al[mt][0], al[mt][1], al[mt][2], al[mt][3], bh[nt][0], bh[nt][1]);
                }
            }
        }
    }
    float* t5b = g_t5 + n * 16384;
    int r0 = lane >> 2, c0 = 2 * (lane & 3);
    #pragma unroll
    for (int mt = 0; mt < 4; mt++) {
        #pragma unroll
        for (int nt = 0; nt < 4; nt++) {
            int row = wm * 64 + mt * 16 + r0, col = wn * 32 + nt * 8 + c0;
            atomicAdd(&t5b[row * 128 + col],           acc[mt][nt][0]);
            atomicAdd(&t5b[row * 128 + col + 1],       acc[mt][nt][1]);
            atomicAdd(&t5b[(row + 8) * 128 + col],     acc[mt][nt][2]);
            atomicAdd(&t5b[(row + 8) * 128 + col + 1], acc[mt][nt][3]);
        }
    }
}

// ---------------------------------------------------------------------------
// K4: prep2 — Am[n][d][c] = w9[c,d]*t5[n,c,d]*scale, split to bf16 hi/lo
// ---------------------------------------------------------------------------
__global__ void k_prep2(const float* __restrict__ w9) {
    int i = blockIdx.x * 256 + threadIdx.x;
    if (i >= Nn * 16384) return;
    int c = i & 127, d = (i >> 7) & 127, n = i >> 14;
    const float SCALE = 1.0f / (112.0f * 11.313708498984761f);
    float v = g_t5[n * 16384 + c * 128 + d] * w9[c * 128 + d] * SCALE;
    __nv_bfloat16 hh, ll;
    bsplit(v, hh, ll);
    g_amh[i] = hh;
    g_aml[i] = ll;
}

// ---------------------------------------------------------------------------
// K5: conv3 via mma: t3[o][w] = sum_{kk,i} w3[o,i,kk]*t2T[w+2kk][i]
// ---------------------------------------------------------------------------
__global__ void __launch_bounds__(256) k_conv3() {
    extern __shared__ __nv_bfloat16 sm3[];
    __nv_bfloat16* sBh = sm3;                   // [132][136]
    __nv_bfloat16* sBl = sm3 + 132 * 136;
    __nv_bfloat16* sAh = sm3 + 2 * 132 * 136;   // [128][136]
    __nv_bfloat16* sAl = sAh + 128 * 136;
    int h = blockIdx.x, n = blockIdx.y, tid = threadIdx.x, lane = tid & 31, warp = tid >> 5;
    int wm = warp >> 2, wn = warp & 3;

    size_t tb = ((size_t)(n * Hh + h)) * T2T_H;
    const __nv_bfloat16 Z = __float2bfloat16(0.f);
    for (int i = tid; i < 132 * 128; i += 256) {
        int wp = i >> 7;
        __nv_bfloat16 vh = Z, vl = Z;
        if (wp < 116) { vh = g_t2Th[tb + i]; vl = g_t2Tl[tb + i]; }
        int c = i & 127;
        sBh[wp * 136 + c] = vh;
        sBl[wp * 136 + c] = vl;
    }

    float acc[4][4][4];
    #pragma unroll
    for (int a = 0; a < 4; a++)
        #pragma unroll
        for (int b = 0; b < 4; b++)
            #pragma unroll
            for (int c = 0; c < 4; c++) acc[a][b][c] = 0.f;

    int qa_row = (lane & 7) + ((lane >> 3) & 1) * 8;
    int qa_col = (lane >> 4) * 8;
    int lb = lane & 15;
    int qb_row = lb & 7, qb_col = (lb >> 3) * 8;
    u32 aH = smem_u32(sAh), aL = smem_u32(sAl), bH = smem_u32(sBh), bL = smem_u32(sBl);

    for (int kk = 0; kk < 3; kk++) {
        __syncthreads();
        for (int i = tid; i < 128 * 128; i += 256) {
            int o = i >> 7, ii = i & 127;
            sAh[o * 136 + ii] = g_w3h[kk * 16384 + i];
            sAl[o * 136 + ii] = g_w3l[kk * 16384 + i];
        }
        __syncthreads();
        int roff = 2 * kk;
        #pragma unroll
        for (int k0 = 0; k0 < 128; k0 += 16) {
            u32 ah[4][4], al[4][4], bh[4][2], bl[4][2];
            #pragma unroll
            for (int mt = 0; mt < 4; mt++) {
                u32 off = (u32)(((wm * 64 + mt * 16 + qa_row) * 136 + k0 + qa_col) * 2);
                ldsm4(ah[mt][0], ah[mt][1], ah[mt][2], ah[mt][3], aH + off);
                ldsm4(al[mt][0], al[mt][1], al[mt][2], al[mt][3], aL + off);
            }
            #pragma unroll
            for (int nt = 0; nt < 4; nt++) {
                u32 off = (u32)(((wn * 32 + nt * 8 + qb_row + roff) * 136 + k0 + qb_col) * 2);
                ldsm2(bh[nt][0], bh[nt][1], bH + off);
                ldsm2(bl[nt][0], bl[nt][1], bL + off);
            }
            #pragma unroll
            for (int mt = 0; mt < 4; mt++) {
                #pragma unroll
                for (int nt = 0; nt < 4; nt++) {
                    mma16816(acc[mt][nt], ah[mt][0], ah[mt][1], ah[mt][2], ah[mt][3], bh[nt][0], bh[nt][1]);
                    mma16816(acc[mt][nt], ah[mt][0], ah[mt][1], ah[mt][2], ah[mt][3], bl[nt][0], bl[nt][1]);
                    mma16816(acc[mt][nt], al[mt][0], al[mt][1], al[mt][2], al[mt][3], bh[nt][0], bh[nt][1]);
                }
            }
        }
    }
    __syncthreads();
    float* ob = (float*)sAh;   // [128][116]
    int r0 = lane >> 2, c0 = 2 * (lane & 3);
    #pragma unroll
    for (int mt = 0; mt < 4; mt++) {
        #pragma unroll
        for (int nt = 0; nt < 4; nt++) {
            int row = wm * 64 + mt * 16 + r0, col = wn * 32 + nt * 8 + c0;
            if (col < 112) {
                ob[row * 116 + col]           = acc[mt][nt][0];
                ob[row * 116 + col + 1]       = acc[mt][nt][1];
                ob[(row + 8) * 116 + col]     = acc[mt][nt][2];
                ob[(row + 8) * 116 + col + 1] = acc[mt][nt][3];
            }
        }
    }
    __syncthreads();
    float* dst = g_t3 + (size_t)n * CHW + (size_t)h * Ww;
    for (int i = tid; i < 128 * 112; i += 256) {
        int o = i / 112, w = i - o * 112;
        dst[(size_t)o * HW + w] = ob[o * 116 + w];
    }
}

// ---------------------------------------------------------------------------
// K6: t4 = depthwise conv (7,1), dil (3,1), pad (9,0) on t3  (scalar, mem-bound)
// ---------------------------------------------------------------------------
__global__ void k_conv4(const float* __restrict__ w4) {
    int idx = blockIdx.x * blockDim.x + threadIdx.x;
    if (idx >= NTOT) return;
    int w = idx % Ww;
    int t = idx / Ww;
    int h = t % Hh;
    int nc = t / Hh;
    int c = nc & 127;
    const float* base = g_t3 + (size_t)nc * HW;
    float wk[7];
    #pragma unroll
    for (int k = 0; k < 7; k++) wk[k] = __ldg(&w4[c * 7 + k]);
    float acc = 0.f;
    #pragma unroll
    for (int k = 0; k < 7; k++) {
        int hh = h - 9 + 3 * k;
        if (hh >= 0 && hh < Hh) acc += base[hh * Ww + w] * wk[k];
    }
    g_t4[idx] = acc;
}

// ---------------------------------------------------------------------------
// K7: t14 via mma: out[d][w] = sum_c Am[n][d][c] * t2T[w+2][c]   (writes out)
// ---------------------------------------------------------------------------
__global__ void __launch_bounds__(256) k_t14(float* __restrict__ out) {
    extern __shared__ __nv_bfloat16 sm4[];
    __nv_bfloat16* sBh = sm4;                   // [128][136]
    __nv_bfloat16* sBl = sm4 + 128 * 136;
    __nv_bfloat16* sAh = sm4 + 2 * 128 * 136;
    __nv_bfloat16* sAl = sm4 + 3 * 128 * 136;
    int h = blockIdx.x, n = blockIdx.y, tid = threadIdx.x, lane = tid & 31, warp = tid >> 5;
    int wm = warp >> 2, wn = warp & 3;

    size_t tb = ((size_t)(n * Hh + h)) * T2T_H;
    const __nv_bfloat16 Z = __float2bfloat16(0.f);
    for (int i = tid; i < 128 * 128; i += 256) {
        int r = i >> 7, c = i & 127;
        __nv_bfloat16 vh = Z, vl = Z;
        if (r < 112) {
            vh = g_t2Th[tb + (size_t)(r + 2) * 128 + c];
            vl = g_t2Tl[tb + (size_t)(r + 2) * 128 + c];
        }
        sBh[r * 136 + c] = vh;
        sBl[r * 136 + c] = vl;
        sAh[r * 136 + c] = g_amh[n * 16384 + i];
        sAl[r * 136 + c] = g_aml[n * 16384 + i];
    }
    __syncthreads();

    float acc[4][4][4];
    #pragma unroll
    for (int a = 0; a < 4; a++)
        #pragma unroll
        for (int b = 0; b < 4; b++)
            #pragma unroll
            for (int c = 0; c < 4; c++) acc[a][b][c] = 0.f;

    int qa_row = (lane & 7) + ((lane >> 3) & 1) * 8;
    int qa_col = (lane >> 4) * 8;
    int lb = lane & 15;
    int qb_row = lb & 7, qb_col = (lb >> 3) * 8;
    u32 aH = smem_u32(sAh), aL = smem_u32(sAl), bH = smem_u32(sBh), bL = smem_u32(sBl);

    #pragma unroll
    for (int k0 = 0; k0 < 128; k0 += 16) {
        u32 ah[4][4], al[4][4], bh[4][2], bl[4][2];
        #pragma unroll
        for (int mt = 0; mt < 4; mt++) {
            u32 off = (u32)(((wm * 64 + mt * 16 + qa_row) * 136 + k0 + qa_col) * 2);
            ldsm4(ah[mt][0], ah[mt][1], ah[mt][2], ah[mt][3], aH + off);
            ldsm4(al[mt][0], al[mt][1], al[mt][2], al[mt][3], aL + off);
        }
        #pragma unroll
        for (int nt = 0; nt < 4; nt++) {
            u32 off = (u32)(((wn * 32 + nt * 8 + qb_row) * 136 + k0 + qb_col) * 2);
            ldsm2(bh[nt][0], bh[nt][1], bH + off);
            ldsm2(bl[nt][0], bl[nt][1], bL + off);
        }
        #pragma unroll
        for (int mt = 0; mt < 4; mt++) {
            #pragma unroll
            for (int nt = 0; nt < 4; nt++) {
                mma16816(acc[mt][nt], ah[mt][0], ah[mt][1], ah[mt][2], ah[mt][3], bh[nt][0], bh[nt][1]);
                mma16816(acc[mt][nt], ah[mt][0], ah[mt][1], ah[mt][2], ah[mt][3], bl[nt][0], bl[nt][1]);
                mma16816(acc[mt][nt], al[mt][0], al[mt][1], al[mt][2], al[mt][3], bh[nt][0], bh[nt][1]);
            }
        }
    }
    __syncthreads();
    float* ob = (float*)sAh;   // [128][116]
    int r0 = lane >> 2, c0 = 2 * (lane & 3);
    #pragma unroll
    for (int mt = 0; mt < 4; mt++) {
        #pragma unroll
        for (int nt = 0; nt < 4; nt++) {
            int row = wm * 64 + mt * 16 + r0, col = wn * 32 + nt * 8 + c0;
            if (col < 112) {
                ob[row * 116 + col]           = acc[mt][nt][0];
                ob[row * 116 + col + 1]       = acc[mt][nt][1];
                ob[(row + 8) * 116 + col]     = acc[mt][nt][2];
                ob[(row + 8) * 116 + col + 1] = acc[mt][nt][3];
            }
        }
    }
    __syncthreads();
    float* dst = out + (size_t)n * CHW + (size_t)h * Ww;
    for (int i = tid; i < 128 * 112; i += 256) {
        int d = i / 112, w = i - d * 112;
        dst[(size_t)d * HW + w] = ob[d * 116 + w];
    }
}

// ---------------------------------------------------------------------------
// K8: out += t15 (scalar gather-GEMM)
// ---------------------------------------------------------------------------
__global__ void __launch_bounds__(256) k_t15(float* __restrict__ out) {
    extern __shared__ float smf[];
    float* rowb = smf;             // [128 c][112 w]
    float* wsm  = smf + 128 * 112; // [32 cc][128 o]
    int h = blockIdx.x, n = blockIdx.y;
    int tid = threadIdx.x, tx = tid & 15, ty = tid >> 4;
    int gbase = (ty >> 2) * 32;
    int h2 = (h + 2) % Hh;
    int wcol[7];
    #pragma unroll
    for (int j = 0; j < 7; j++) wcol[j] = (tx + 16 * j + 110) % 112;
    float acc[8][7];
    #pragma unroll
    for (int i = 0; i < 8; i++)
        #pragma unroll
        for (int j = 0; j < 7; j++) acc[i][j] = 0.f;

    for (int k = 0; k < 7; k++) {
        int r = h2 + 2 * k - 6;
        if (r < 0 || r >= Hh) continue;
        __syncthreads();
        const float* t4row = g_t4 + (size_t)n * CHW + (size_t)r * Ww;
        for (int i = tid; i < 128 * 112; i += 256) {
            int c = i / 112, w = i - c * 112;
            rowb[c * 112 + w] = t4row[(size_t)c * HW + w];
        }
        for (int i = tid; i < 32 * 128; i += 256) wsm[i] = g_weff[k * 4096 + i];
        __syncthreads();
        #pragma unroll 4
        for (int cc = 0; cc < 32; cc++) {
            int c2 = (gbase + cc - 2) & 127;
            const float* ar = wsm + cc * 128 + ty * 8;
            float a[8];
            #pragma unroll
            for (int i = 0; i < 8; i++) a[i] = ar[i];
            const float* br = rowb + c2 * 112;
            #pragma unroll
            for (int j = 0; j < 7; j++) {
                float b = br[wcol[j]];
                #pragma unroll
                for (int i = 0; i < 8; i++) acc[i][j] += a[i] * b;
            }
        }
    }
    float* dst = out + (size_t)n * CHW + (size_t)h * Ww;
    #pragma unroll
    for (int i = 0; i < 8; i++) {
        int o = ty * 8 + i;
        #pragma unroll
        for (int j = 0; j < 7; j++)
            dst[(size_t)o * HW + tx + 16 * j] += acc[i][j];
    }
}

// ---------------------------------------------------------------------------
extern "C" void kernel_launch(void* const* d_in, const int* in_sizes, int n_in,
                              void* d_out, int out_size) {
    const float* x   = (const float*)d_in[0];
    const float* w3  = (const float*)d_in[1];
    const float* w4  = (const float*)d_in[2];
    const float* w9  = (const float*)d_in[3];
    const float* w10 = (const float*)d_in[4];
    const float* w15 = (const float*)d_in[5];
    float* out = (float*)d_out;

    const int SMEM_SILU = 128 * 113 * 4;                        // 57856
    const int SMEM_T5   = 4 * 128 * 72 * 2;                     // 73728
    const int SMEM_C3   = (2 * 132 * 136 + 2 * 128 * 136) * 2;  // 141440
    const int SMEM_T14  = 4 * 128 * 136 * 2;                    // 139264
    const int SMEM_T15  = (128 * 112 + 32 * 128) * 4;           // 73728
    cudaFuncSetAttribute(k_silu_t, cudaFuncAttributeMaxDynamicSharedMemorySize, SMEM_SILU);
    cudaFuncSetAttribute(k_t5,     cudaFuncAttributeMaxDynamicSharedMemorySize, SMEM_T5);
    cudaFuncSetAttribute(k_conv3,  cudaFuncAttributeMaxDynamicSharedMemorySize, SMEM_C3);
    cudaFuncSetAttribute(k_t14,    cudaFuncAttributeMaxDynamicSharedMemorySize, SMEM_T14);
    cudaFuncSetAttribute(k_t15,    cudaFuncAttributeMaxDynamicSharedMemorySize, SMEM_T15);

    k_silu_t<<< dim3(112, 8), 256, SMEM_SILU >>>(x);
    k_prep  <<< 512, 256 >>>(w3, w10, w15);
    k_t5    <<< dim3(28, 8), 256, SMEM_T5 >>>(x);
    k_prep2 <<< 512, 256 >>>(w9);
    k_conv3 <<< dim3(112, 8), 256, SMEM_C3 >>>();
    k_conv4 <<< (NTOT + 255) / 256, 256 >>>(w4);
    k_t14   <<< dim3(112, 8), 256, SMEM_T14 >>>(out);
    k_t15   <<< dim3(112, 8), 256, SMEM_T15 >>>(out);
}